// round 8
// baseline (speedup 1.0000x reference)
#include <cuda_runtime.h>
#include <cuda_fp16.h>
#include <math.h>

// Persistent device scratch (no allocation allowed in kernel_launch).
__device__ __half g_score_h[100032];   // fp16 score table (padded)
__device__ int    g_sink[512];         // write-only sink for prefetch checksums

// ---------------------------------------------------------------------------
// Kernel 1: per-node features + MLP (3->32->32->1) + sigmoid -> fp16 table.
// Master node: setup pins it at node 0 (x_t[0,0]==1.0); fallback scan kept
// for arbitrary inputs. After writing its scores, each block also streams a
// slice of the edge-index array to warm L2 (checksummed into g_sink so the
// loads survive DCE) — this runs under the shadow of the FMA-bound MLP and
// converts the gather kernel's index loads from DRAM misses into L2 hits.
// ---------------------------------------------------------------------------
#define NS_THREADS 256
__global__ void node_score_kernel(const float* __restrict__ x_t,
                                  const float* __restrict__ x_t_dt,
                                  const float* __restrict__ W1,
                                  const float* __restrict__ b1,
                                  const float* __restrict__ W2,
                                  const float* __restrict__ b2,
                                  const float* __restrict__ W3,
                                  const float* __restrict__ b3,
                                  const int4* __restrict__ tgt4,
                                  int n_tgt4,
                                  int n_nodes) {
    __shared__ float sW1[96];
    __shared__ float sb1[32];
    __shared__ __align__(16) float sW2[1024];
    __shared__ float sb2[32];
    __shared__ float sW3[32];
    __shared__ float sb3;
    __shared__ float smx, smy, smz;
    __shared__ __align__(16) float sx[NS_THREADS * 7];
    __shared__ __align__(16) float sxd[NS_THREADS * 7];

    int t = threadIdx.x;
    for (int k = t; k < 96; k += NS_THREADS) sW1[k] = W1[k];
    for (int k = t; k < 1024; k += NS_THREADS) sW2[k] = W2[k];
    if (t < 32) {
        sb1[t] = b1[t];
        sb2[t] = b2[t];
        sW3[t] = W3[t];
    }
    if (t == 0) {
        sb3 = b3[0];
        // Master position: fast path (node 0 is the master by construction).
        if (__ldg(&x_t[0]) == 1.0f) {
            smx = __ldg(&x_t[1]);
            smy = __ldg(&x_t[2]);
            smz = __ldg(&x_t[3]);
        } else {
            // Fallback: serial scan (never taken for bench inputs).
            for (int i = 1; i < n_nodes; i++) {
                if (__ldg(&x_t[(size_t)i * 7]) == 1.0f) {
                    smx = __ldg(&x_t[(size_t)i * 7 + 1]);
                    smy = __ldg(&x_t[(size_t)i * 7 + 2]);
                    smz = __ldg(&x_t[(size_t)i * 7 + 3]);
                    break;
                }
            }
        }
    }

    // Coalesced staging of this block's node rows.
    int base_node = blockIdx.x * NS_THREADS;
    int nrows = min(NS_THREADS, n_nodes - base_node);
    int nflt = nrows * 7;
    const float* xr  = x_t    + (size_t)base_node * 7;
    const float* xdr = x_t_dt + (size_t)base_node * 7;
    for (int k = t; k < nflt; k += NS_THREADS) {
        sx[k]  = xr[k];
        sxd[k] = xdr[k];
    }
    __syncthreads();

    if (t < nrows) {
        int i = base_node + t;

        float px = sx[t * 7 + 1];
        float py = sx[t * 7 + 2];
        float pz = sx[t * 7 + 3];
        float dx = sxd[t * 7 + 1] - px;
        float dy = sxd[t * 7 + 2] - py;
        float dz = sxd[t * 7 + 3] - pz;

        float dn = sqrtf(dx * dx + dy * dy + dz * dz);   // velocity_score
        float inv_dn = 1.0f / fmaxf(dn, 1e-12f);         // dt = 1
        float vx = dx * inv_dn, vy = dy * inv_dn, vz = dz * inv_dn;

        float rx = px - smx, ry = py - smy, rz = pz - smz;
        float rn = sqrtf(rx * rx + ry * ry + rz * rz);
        float dist = rn + 1e-6f;
        float na = fmaxf(rn, 1e-6f);
        float nb = fmaxf(sqrtf(vx * vx + vy * vy + vz * vz), 1e-6f);
        float dir_score = (rx * vx + ry * vy + rz * vz) / (na * nb);

        float a0 = 1.0f / dist;
        float a1 = dir_score;
        float a2 = dn;

        // Layer 1: 3 -> 32
        float h[32];
#pragma unroll
        for (int j = 0; j < 32; j++) {
            float s = fmaf(a2, sW1[j * 3 + 2],
                     fmaf(a1, sW1[j * 3 + 1],
                     fmaf(a0, sW1[j * 3 + 0], sb1[j])));
            h[j] = fmaxf(s, 0.0f);
        }

        // Layer 2: 32 -> 32 with vectorized weight reads (LDS.128)
        const float4* w2v = reinterpret_cast<const float4*>(sW2);
        float h2[32];
#pragma unroll
        for (int j = 0; j < 32; j++) {
            float s = sb2[j];
#pragma unroll
            for (int k4 = 0; k4 < 8; k4++) {
                float4 w = w2v[j * 8 + k4];
                s = fmaf(h[k4 * 4 + 0], w.x, s);
                s = fmaf(h[k4 * 4 + 1], w.y, s);
                s = fmaf(h[k4 * 4 + 2], w.z, s);
                s = fmaf(h[k4 * 4 + 3], w.w, s);
            }
            h2[j] = fmaxf(s, 0.0f);
        }

        // Layer 3: 32 -> 1, sigmoid
        float s = sb3;
#pragma unroll
        for (int k = 0; k < 32; k++) s = fmaf(h2[k], sW3[k], s);
        float sig = 1.0f / (1.0f + __expf(-s));
        g_score_h[i] = __float2half(sig);
    }

    // L2 warm-up of the edge-index array (overlaps with other blocks' math).
    // Grid-stride over int4 groups; checksum into a write-only sink.
    {
        int gstride = gridDim.x * NS_THREADS;
        int acc = 0;
        for (int k = blockIdx.x * NS_THREADS + t; k < n_tgt4; k += gstride) {
            int4 v = __ldg(&tgt4[k]);
            acc += v.x + v.y + v.z + v.w;
        }
        if (acc == 0x7FFFFFFF) g_sink[blockIdx.x & 511] = acc;  // never true
    }
}

// ---------------------------------------------------------------------------
// Kernel 2: persistent gather, 4x unrolled. Table in SMEM (200KB fp16);
// index loads now hit L2 thanks to the prefetch in kernel 1.
// ---------------------------------------------------------------------------
#define G_THREADS 1024
__global__ void gather_kernel(const int* __restrict__ tgt,
                              float* __restrict__ out,
                              int n_edges, int n_nodes) {
    extern __shared__ __align__(16) __half stab[];

    // Cooperative table load (uint4 = 8 halves, coalesced).
    int n8 = (n_nodes + 7) >> 3;
    const uint4* src = reinterpret_cast<const uint4*>(g_score_h);
    uint4* dst = reinterpret_cast<uint4*>(stab);
    for (int k = threadIdx.x; k < n8; k += G_THREADS) dst[k] = src[k];
    __syncthreads();

    int n4 = n_edges >> 2;                    // number of int4 groups
    int stride = gridDim.x * G_THREADS;
    const int4* tv = reinterpret_cast<const int4*>(tgt);
    float4* ov = reinterpret_cast<float4*>(out);

    int j = blockIdx.x * G_THREADS + threadIdx.x;

    for (; j + 3 * stride < n4; j += 4 * stride) {
        int4 a0 = tv[j];
        int4 a1 = tv[j + stride];
        int4 a2 = tv[j + 2 * stride];
        int4 a3 = tv[j + 3 * stride];
        float4 o0, o1, o2, o3;
        o0.x = __half2float(stab[a0.x]); o0.y = __half2float(stab[a0.y]);
        o0.z = __half2float(stab[a0.z]); o0.w = __half2float(stab[a0.w]);
        o1.x = __half2float(stab[a1.x]); o1.y = __half2float(stab[a1.y]);
        o1.z = __half2float(stab[a1.z]); o1.w = __half2float(stab[a1.w]);
        o2.x = __half2float(stab[a2.x]); o2.y = __half2float(stab[a2.y]);
        o2.z = __half2float(stab[a2.z]); o2.w = __half2float(stab[a2.w]);
        o3.x = __half2float(stab[a3.x]); o3.y = __half2float(stab[a3.y]);
        o3.z = __half2float(stab[a3.z]); o3.w = __half2float(stab[a3.w]);
        ov[j]              = o0;
        ov[j + stride]     = o1;
        ov[j + 2 * stride] = o2;
        ov[j + 3 * stride] = o3;
    }
    for (; j < n4; j += stride) {
        int4 a = tv[j];
        float4 o;
        o.x = __half2float(stab[a.x]);
        o.y = __half2float(stab[a.y]);
        o.z = __half2float(stab[a.z]);
        o.w = __half2float(stab[a.w]);
        ov[j] = o;
    }

    if (blockIdx.x == 0 && threadIdx.x == 0) {
        for (int e = n4 << 2; e < n_edges; e++)
            out[e] = __half2float(stab[tgt[e]]);
    }
}

extern "C" void kernel_launch(void* const* d_in, const int* in_sizes, int n_in,
                              void* d_out, int out_size) {
    const float* x_t    = (const float*)d_in[0];
    const float* x_t_dt = (const float*)d_in[1];
    const int*   edge_index = (const int*)d_in[2];   // int32 (JAX x64 off)
    const float* W1 = (const float*)d_in[3];
    const float* b1 = (const float*)d_in[4];
    const float* W2 = (const float*)d_in[5];
    const float* b2 = (const float*)d_in[6];
    const float* W3 = (const float*)d_in[7];
    const float* b3 = (const float*)d_in[8];
    float* out = (float*)d_out;

    int n_nodes = in_sizes[0] / 7;
    int n_edges = in_sizes[2] / 2;
    const int* tgt = edge_index + n_edges;  // row 1 of (2, E)
    int n_tgt4 = n_edges >> 2;

    // Kernel 1: node scores + L2 prefetch of the index array.
    int nb_nodes = (n_nodes + NS_THREADS - 1) / NS_THREADS;
    node_score_kernel<<<nb_nodes, NS_THREADS>>>(
        x_t, x_t_dt, W1, b1, W2, b2, W3, b3,
        (const int4*)tgt, n_tgt4, n_nodes);

    // Kernel 2: persistent gather with SMEM-resident fp16 table.
    size_t smem = ((size_t)(n_nodes + 7) & ~7ull) * sizeof(__half);
    cudaFuncSetAttribute(gather_kernel,
                         cudaFuncAttributeMaxDynamicSharedMemorySize,
                         (int)smem + 16);
    gather_kernel<<<148, G_THREADS, smem>>>(tgt, out, n_edges, n_nodes);
}

// round 10
// speedup vs baseline: 1.2762x; 1.2762x over previous
#include <cuda_runtime.h>
#include <cuda_fp16.h>
#include <math.h>

// Persistent device scratch (no allocation allowed in kernel_launch).
__device__ __half g_score_h[100032];   // fp16 score table (padded)

#define NS_BLOCKS 148
#define NS_THREADS 512

// ---------------------------------------------------------------------------
// Kernel 1: persistent node-score kernel (148 blocks = 1 per SM, no wave
// tail). Each block processes a contiguous range of nodes in 512-row chunks:
// coalesced SMEM staging of the stride-7 rows, then features + MLP. Layer 3
// is folded into the layer-2 loop so h2[] never materializes.
// Master node: setup pins it at node 0 (x_t[0,0]==1.0); serial fallback scan
// keeps correctness for arbitrary inputs (never taken on bench data).
// ---------------------------------------------------------------------------
__global__ void __launch_bounds__(NS_THREADS, 1)
node_score_kernel(const float* __restrict__ x_t,
                  const float* __restrict__ x_t_dt,
                  const float* __restrict__ W1,
                  const float* __restrict__ b1,
                  const float* __restrict__ W2,
                  const float* __restrict__ b2,
                  const float* __restrict__ W3,
                  const float* __restrict__ b3,
                  int n_nodes) {
    __shared__ float sW1[96];
    __shared__ float sb1[32];
    __shared__ __align__(16) float sW2[1024];
    __shared__ float sb2[32];
    __shared__ float sW3[32];
    __shared__ float sb3;
    __shared__ float smx, smy, smz;
    __shared__ __align__(16) float sx[NS_THREADS * 7];
    __shared__ __align__(16) float sxd[NS_THREADS * 7];

    int t = threadIdx.x;

    // Stage weights once per block (148 blocks total, not 391).
    for (int k = t; k < 96; k += NS_THREADS) sW1[k] = W1[k];
    for (int k = t; k < 1024; k += NS_THREADS) sW2[k] = W2[k];
    if (t < 32) {
        sb1[t] = b1[t];
        sb2[t] = b2[t];
        sW3[t] = W3[t];
    }
    if (t == 0) {
        sb3 = b3[0];
        if (__ldg(&x_t[0]) == 1.0f) {           // fast path: master is node 0
            smx = __ldg(&x_t[1]);
            smy = __ldg(&x_t[2]);
            smz = __ldg(&x_t[3]);
        } else {                                 // fallback (never taken)
            for (int i = 1; i < n_nodes; i++) {
                if (__ldg(&x_t[(size_t)i * 7]) == 1.0f) {
                    smx = __ldg(&x_t[(size_t)i * 7 + 1]);
                    smy = __ldg(&x_t[(size_t)i * 7 + 2]);
                    smz = __ldg(&x_t[(size_t)i * 7 + 3]);
                    break;
                }
            }
        }
    }

    // This block's node range.
    int npb = (n_nodes + NS_BLOCKS - 1) / NS_BLOCKS;
    int node_beg = blockIdx.x * npb;
    int node_end = min(node_beg + npb, n_nodes);

    for (int base = node_beg; base < node_end; base += NS_THREADS) {
        int nrows = min(NS_THREADS, node_end - base);
        int nflt = nrows * 7;
        const float* xr  = x_t    + (size_t)base * 7;
        const float* xdr = x_t_dt + (size_t)base * 7;
        for (int k = t; k < nflt; k += NS_THREADS) {
            sx[k]  = xr[k];
            sxd[k] = xdr[k];
        }
        __syncthreads();

        if (t < nrows) {
            float px = sx[t * 7 + 1];
            float py = sx[t * 7 + 2];
            float pz = sx[t * 7 + 3];
            float dx = sxd[t * 7 + 1] - px;
            float dy = sxd[t * 7 + 2] - py;
            float dz = sxd[t * 7 + 3] - pz;

            float dn = sqrtf(dx * dx + dy * dy + dz * dz);  // velocity_score
            float inv_dn = 1.0f / fmaxf(dn, 1e-12f);        // dt = 1
            float vx = dx * inv_dn, vy = dy * inv_dn, vz = dz * inv_dn;

            float rx = px - smx, ry = py - smy, rz = pz - smz;
            float rn = sqrtf(rx * rx + ry * ry + rz * rz);
            float dist = rn + 1e-6f;
            float na = fmaxf(rn, 1e-6f);
            float nb = fmaxf(sqrtf(vx * vx + vy * vy + vz * vz), 1e-6f);
            float dir_score = (rx * vx + ry * vy + rz * vz) / (na * nb);

            float a0 = 1.0f / dist;
            float a1 = dir_score;
            float a2 = dn;

            // Layer 1: 3 -> 32
            float h[32];
#pragma unroll
            for (int j = 0; j < 32; j++) {
                float s = fmaf(a2, sW1[j * 3 + 2],
                         fmaf(a1, sW1[j * 3 + 1],
                         fmaf(a0, sW1[j * 3 + 0], sb1[j])));
                h[j] = fmaxf(s, 0.0f);
            }

            // Layers 2+3 fused: each h2[j] folded directly into layer-3 dot.
            const float4* w2v = reinterpret_cast<const float4*>(sW2);
            float s3 = sb3;
#pragma unroll
            for (int j = 0; j < 32; j++) {
                float s = sb2[j];
#pragma unroll
                for (int k4 = 0; k4 < 8; k4++) {
                    float4 w = w2v[j * 8 + k4];
                    s = fmaf(h[k4 * 4 + 0], w.x, s);
                    s = fmaf(h[k4 * 4 + 1], w.y, s);
                    s = fmaf(h[k4 * 4 + 2], w.z, s);
                    s = fmaf(h[k4 * 4 + 3], w.w, s);
                }
                s3 = fmaf(fmaxf(s, 0.0f), sW3[j], s3);
            }
            float sig = 1.0f / (1.0f + __expf(-s3));
            g_score_h[base + t] = __float2half(sig);
        }
        __syncthreads();   // staging buffers reused next chunk
    }
}

// ---------------------------------------------------------------------------
// Kernel 2: persistent gather (R7 form, measured 14.5us). Table in SMEM
// (200KB fp16); 4x unrolled: int4 index loads front-batched, LDS.U16
// lookups, float4 stores.
// ---------------------------------------------------------------------------
#define G_THREADS 1024
__global__ void gather_kernel(const int* __restrict__ tgt,
                              float* __restrict__ out,
                              int n_edges, int n_nodes) {
    extern __shared__ __align__(16) __half stab[];

    int n8 = (n_nodes + 7) >> 3;
    const uint4* src = reinterpret_cast<const uint4*>(g_score_h);
    uint4* dst = reinterpret_cast<uint4*>(stab);
    for (int k = threadIdx.x; k < n8; k += G_THREADS) dst[k] = src[k];
    __syncthreads();

    int n4 = n_edges >> 2;
    int stride = gridDim.x * G_THREADS;
    const int4* tv = reinterpret_cast<const int4*>(tgt);
    float4* ov = reinterpret_cast<float4*>(out);

    int j = blockIdx.x * G_THREADS + threadIdx.x;

    for (; j + 3 * stride < n4; j += 4 * stride) {
        int4 a0 = tv[j];
        int4 a1 = tv[j + stride];
        int4 a2 = tv[j + 2 * stride];
        int4 a3 = tv[j + 3 * stride];
        float4 o0, o1, o2, o3;
        o0.x = __half2float(stab[a0.x]); o0.y = __half2float(stab[a0.y]);
        o0.z = __half2float(stab[a0.z]); o0.w = __half2float(stab[a0.w]);
        o1.x = __half2float(stab[a1.x]); o1.y = __half2float(stab[a1.y]);
        o1.z = __half2float(stab[a1.z]); o1.w = __half2float(stab[a1.w]);
        o2.x = __half2float(stab[a2.x]); o2.y = __half2float(stab[a2.y]);
        o2.z = __half2float(stab[a2.z]); o2.w = __half2float(stab[a2.w]);
        o3.x = __half2float(stab[a3.x]); o3.y = __half2float(stab[a3.y]);
        o3.z = __half2float(stab[a3.z]); o3.w = __half2float(stab[a3.w]);
        ov[j]              = o0;
        ov[j + stride]     = o1;
        ov[j + 2 * stride] = o2;
        ov[j + 3 * stride] = o3;
    }
    for (; j < n4; j += stride) {
        int4 a = tv[j];
        float4 o;
        o.x = __half2float(stab[a.x]);
        o.y = __half2float(stab[a.y]);
        o.z = __half2float(stab[a.z]);
        o.w = __half2float(stab[a.w]);
        ov[j] = o;
    }

    if (blockIdx.x == 0 && threadIdx.x == 0) {
        for (int e = n4 << 2; e < n_edges; e++)
            out[e] = __half2float(stab[tgt[e]]);
    }
}

extern "C" void kernel_launch(void* const* d_in, const int* in_sizes, int n_in,
                              void* d_out, int out_size) {
    const float* x_t    = (const float*)d_in[0];
    const float* x_t_dt = (const float*)d_in[1];
    const int*   edge_index = (const int*)d_in[2];   // int32 (JAX x64 off)
    const float* W1 = (const float*)d_in[3];
    const float* b1 = (const float*)d_in[4];
    const float* W2 = (const float*)d_in[5];
    const float* b2 = (const float*)d_in[6];
    const float* W3 = (const float*)d_in[7];
    const float* b3 = (const float*)d_in[8];
    float* out = (float*)d_out;

    int n_nodes = in_sizes[0] / 7;
    int n_edges = in_sizes[2] / 2;
    const int* tgt = edge_index + n_edges;  // row 1 of (2, E)

    // Kernel 1: persistent node scores (no wave tail, weights loaded once).
    node_score_kernel<<<NS_BLOCKS, NS_THREADS>>>(
        x_t, x_t_dt, W1, b1, W2, b2, W3, b3, n_nodes);

    // Kernel 2: persistent gather with SMEM-resident fp16 table.
    size_t smem = ((size_t)(n_nodes + 7) & ~7ull) * sizeof(__half);
    cudaFuncSetAttribute(gather_kernel,
                         cudaFuncAttributeMaxDynamicSharedMemorySize,
                         (int)smem + 16);
    gather_kernel<<<148, G_THREADS, smem>>>(tgt, out, n_edges, n_nodes);
}